// round 2
// baseline (speedup 1.0000x reference)
#include <cuda_runtime.h>
#include <cuda_bf16.h>

// LIF neuron update (SpikeLayer.update_neurons), one timestep.
// Elementwise over SHAPE=(16,56,56,256), N = 12,845,056 fp32 elements.
// Inputs:  impulse, mem, mem_acc, refrac_until, spikecounts   (5 x N fp32)
// Output:  stack([spikes, mem_out, mem_acc_out, refrac_out, counts_out, spiketrain])
//          = 6 x N fp32 at d_out.
//
// Constants: V_THRESH=1.0, DT=1.0, TAU_REFRAC=2.0, TIME=0.5

#define V_THRESH 1.0f
#define TIME_C   0.5f
#define REFRAC_NEW 2.5f   // TIME + TAU_REFRAC

__global__ void __launch_bounds__(256) lif_update_kernel(
    const float4* __restrict__ impulse,
    const float4* __restrict__ mem,
    const float4* __restrict__ mem_acc,
    const float4* __restrict__ refrac_until,
    const float4* __restrict__ spikecounts,
    float4* __restrict__ out,     // 6 planes of n4 float4 each
    int n4)
{
    int i = blockIdx.x * blockDim.x + threadIdx.x;
    if (i >= n4) return;

    // Front-batch all 5 loads for max MLP.
    float4 imp = impulse[i];
    float4 m   = mem[i];
    float4 ma  = mem_acc[i];
    float4 ru  = refrac_until[i];
    float4 sc  = spikecounts[i];

    float4 o_spk, o_mem, o_macc, o_ru, o_cnt, o_st;

    #pragma unroll
    for (int c = 0; c < 4; c++) {
        float impv = (&imp.x)[c];
        float mv   = (&m.x)[c];
        float mav  = (&ma.x)[c];
        float ruv  = (&ru.x)[c];
        float scv  = (&sc.x)[c];

        float masked   = (ruv > TIME_C) ? 0.0f : impv;
        float new_mem  = mv + masked;
        float new_macc = mav + masked;
        bool  fire     = (new_mem >= V_THRESH);
        float spike    = fire ? V_THRESH : 0.0f;
        float mem_out  = fire ? (new_mem - V_THRESH) : new_mem;
        float ru_out   = fire ? REFRAC_NEW : ruv;
        float cnt_out  = scv + (fire ? 1.0f : 0.0f);
        float st_out   = spike * TIME_C;

        (&o_spk.x)[c]  = spike;
        (&o_mem.x)[c]  = mem_out;
        (&o_macc.x)[c] = new_macc;
        (&o_ru.x)[c]   = ru_out;
        (&o_cnt.x)[c]  = cnt_out;
        (&o_st.x)[c]   = st_out;
    }

    out[0 * (size_t)n4 + i] = o_spk;
    out[1 * (size_t)n4 + i] = o_mem;
    out[2 * (size_t)n4 + i] = o_macc;
    out[3 * (size_t)n4 + i] = o_ru;
    out[4 * (size_t)n4 + i] = o_cnt;
    out[5 * (size_t)n4 + i] = o_st;
}

extern "C" void kernel_launch(void* const* d_in, const int* in_sizes, int n_in,
                              void* d_out, int out_size)
{
    const float* impulse      = (const float*)d_in[0];
    const float* mem          = (const float*)d_in[1];
    const float* mem_acc      = (const float*)d_in[2];
    const float* refrac_until = (const float*)d_in[3];
    const float* spikecounts  = (const float*)d_in[4];

    int n  = in_sizes[0];       // 12,845,056
    int n4 = n / 4;             // divisible by 4 (last dim = 256)

    int threads = 256;
    int blocks  = (n4 + threads - 1) / threads;

    lif_update_kernel<<<blocks, threads>>>(
        (const float4*)impulse,
        (const float4*)mem,
        (const float4*)mem_acc,
        (const float4*)refrac_until,
        (const float4*)spikecounts,
        (float4*)d_out,
        n4);
}